// round 11
// baseline (speedup 1.0000x reference)
#include <cuda_runtime.h>

typedef unsigned long long ull;

#define NTHREADS 256
#define GPART 32

#define WTOT 2152
#define BTOT 128
__constant__ float c_W[WTOT];
__constant__ float c_b[BTOT];
__device__ float g_wst[WTOT];
__device__ float g_bst[BTOT];

#define SLOT 14     // u64 stride per (point, unit-pair) slot (112 B; quad perm (7w+c)%8)
#define WSW  280    // per-warp smem in u64 (20 slots * 14)

// ---------------- packed f32x2 helpers (sm_103a) ----------------
__device__ __forceinline__ ull fma2(ull a, ull b, ull c) {
    ull d; asm("fma.rn.f32x2 %0,%1,%2,%3;" : "=l"(d) : "l"(a), "l"(b), "l"(c)); return d;
}
__device__ __forceinline__ ull mul2(ull a, ull b) {
    ull d; asm("mul.rn.f32x2 %0,%1,%2;" : "=l"(d) : "l"(a), "l"(b)); return d;
}
__device__ __forceinline__ ull pack2(float lo, float hi) {
    ull d; asm("mov.b64 %0,{%1,%2};" : "=l"(d) : "f"(lo), "f"(hi)); return d;
}
__device__ __forceinline__ void unpack2(ull v, float& lo, float& hi) {
    asm("mov.b64 {%0,%1},%2;" : "=f"(lo), "=f"(hi) : "l"(v));
}
__device__ __forceinline__ float tanh_fast(float x) {
    float y; asm("tanh.approx.f32 %0, %1;" : "=f"(y) : "f"(x));
    return y;
}

#define ONE2     0x3F8000003F800000ull
#define NEGONE2  0xBF800000BF800000ull
#define NEGTWO2  0xC0000000C0000000ull
#define SIX2     0x40C0000040C00000ull
#define NEGFOUR2 0xC0800000C0800000ull
#define NEGSIX2  0xC0C00000C0C00000ull

// ---------------- lb/ub reduction ----------------
__device__ unsigned g_pmin[GPART];
__device__ unsigned g_pmax[GPART];

__device__ __forceinline__ unsigned enc_f(float f) {
    unsigned u = __float_as_uint(f);
    return (u & 0x80000000u) ? ~u : (u | 0x80000000u);
}
__device__ __forceinline__ float dec_f(unsigned e) {
    unsigned u = (e & 0x80000000u) ? (e ^ 0x80000000u) : ~e;
    return __uint_as_float(u);
}

__global__ void k_partial_minmax(const float* __restrict__ X, int n) {
    __shared__ unsigned smn[8], smx[8];
    unsigned mn = 0xFFFFFFFFu, mx = 0u;
    for (int i = blockIdx.x * blockDim.x + threadIdx.x; i < n;
         i += gridDim.x * blockDim.x) {
        unsigned e = enc_f(X[3 * i]);
        mn = min(mn, e); mx = max(mx, e);
    }
    #pragma unroll
    for (int o = 16; o; o >>= 1) {
        mn = min(mn, __shfl_xor_sync(0xffffffffu, mn, o));
        mx = max(mx, __shfl_xor_sync(0xffffffffu, mx, o));
    }
    int w = threadIdx.x >> 5;
    if ((threadIdx.x & 31) == 0) { smn[w] = mn; smx[w] = mx; }
    __syncthreads();
    if (threadIdx.x == 0) {
        #pragma unroll
        for (int i = 1; i < 8; i++) { mn = min(mn, smn[i]); mx = max(mx, smx[i]); }
        g_pmin[blockIdx.x] = mn;
        g_pmax[blockIdx.x] = mx;
    }
}

__global__ void k_nop() {}   // stream-slot filler so ncu -s 5 lands on pinn_kernel

// repack weights into padded float layout in __device__ staging
__global__ void k_repack(const float* __restrict__ W1, const float* __restrict__ b1,
                         const float* __restrict__ W2, const float* __restrict__ b2,
                         const float* __restrict__ W3, const float* __restrict__ b3,
                         const float* __restrict__ W4, const float* __restrict__ b4,
                         const float* __restrict__ W5, const float* __restrict__ b5,
                         const float* __restrict__ W6, const float* __restrict__ b6,
                         const float* __restrict__ W7, const float* __restrict__ b7,
                         const float* __restrict__ W8, const float* __restrict__ b8) {
    const int WOFF[8] = {0, 12, 72, 472, 872, 1272, 1672, 2072};
    const int LDIN[8] = {3, 3, 20, 20, 20, 20, 20, 20};
    const int DSRC[8] = {3, 20, 20, 20, 20, 20, 20, 2};
    const int DPAD[8] = {4, 20, 20, 20, 20, 20, 20, 4};
    const int BOFF[8] = {0, 4, 24, 44, 64, 84, 104, 124};
    const float* Wg[8] = {W1, W2, W3, W4, W5, W6, W7, W8};
    const float* Bg[8] = {b1, b2, b3, b4, b5, b6, b7, b8};
    int tid = threadIdx.x;
    #pragma unroll
    for (int l = 0; l < 8; l++) {
        int tot = LDIN[l] * DPAD[l];
        for (int i = tid; i < tot; i += NTHREADS) {
            int r = i / DPAD[l], c = i % DPAD[l];
            g_wst[WOFF[l] + i] = (c < DSRC[l]) ? Wg[l][r * DSRC[l] + c] : 0.0f;
        }
        for (int i = tid; i < DPAD[l]; i += NTHREADS)
            g_bst[BOFF[l] + i] = (i < DSRC[l]) ? Bg[l][i] : 0.0f;
    }
}

// Jet order: 0:val 1:x 2:y 3:t 4:xx 5:xy 6:yy 7:xt 8:yt 9:xxx 10:xxy 11:xyy 12:yyy
// Per-warp smem: 20 slots (2 points x 10 unit-pairs), slot w at Sw[w*14 .. w*14+12]
// Slot u64 j = (z[2q], z[2q+1]) of jet j for that point.

template <bool LAST>
__device__ __forceinline__ void itemB(ull* __restrict__ Sw, int w, int p,
                                      float* __restrict__ out, int n, int wbase,
                                      float l1, float l2)
{
    ull* B = Sw + w * SLOT;
    ull zj[13];
    #pragma unroll
    for (int c = 0; c < 6; c++) {
        ulonglong2 v = reinterpret_cast<const ulonglong2*>(B)[c];
        zj[2 * c] = v.x; zj[2 * c + 1] = v.y;
    }
    zj[12] = B[12];

    float t0, t1; unpack2(zj[0], t0, t1);
    ull t   = pack2(tanh_fast(t0), tanh_fast(t1));
    ull hq  = mul2(t, t);
    ull sv  = fma2(hq, NEGONE2, ONE2);     // s = 1 - t^2
    ull C   = fma2(hq, SIX2, NEGTWO2);     // 6t^2 - 2
    ull n2h = mul2(t, NEGTWO2);
    ull n4h = mul2(t, NEGFOUR2);
    ull n6h = mul2(t, NEGSIX2);
    ull p11 = mul2(zj[1], zj[1]);
    ull p12 = mul2(zj[1], zj[2]);
    ull p22 = mul2(zj[2], zj[2]);
    ull p13 = mul2(zj[1], zj[3]);
    ull p23 = mul2(zj[2], zj[3]);

    ull hj[13];
    hj[0] = t;
    hj[1] = mul2(sv, zj[1]);
    hj[2] = mul2(sv, zj[2]);
    hj[3] = mul2(sv, zj[3]);
    hj[4] = mul2(sv, fma2(n2h, p11, zj[4]));
    hj[5] = mul2(sv, fma2(n2h, p12, zj[5]));
    hj[6] = mul2(sv, fma2(n2h, p22, zj[6]));
    hj[7] = mul2(sv, fma2(n2h, p13, zj[7]));
    hj[8] = mul2(sv, fma2(n2h, p23, zj[8]));
    {   // xxx
        ull r = fma2(n6h, mul2(zj[1], zj[4]), zj[9]);
        r = fma2(C, mul2(zj[1], p11), r);
        hj[9] = mul2(sv, r);
    }
    {   // xxy
        ull r = fma2(n2h, mul2(zj[2], zj[4]), zj[10]);
        r = fma2(n4h, mul2(zj[1], zj[5]), r);
        r = fma2(C, mul2(p11, zj[2]), r);
        hj[10] = mul2(sv, r);
    }
    {   // xyy
        ull r = fma2(n4h, mul2(zj[2], zj[5]), zj[11]);
        r = fma2(n2h, mul2(zj[1], zj[6]), r);
        r = fma2(C, mul2(zj[1], p22), r);
        hj[11] = mul2(sv, r);
    }
    {   // yyy
        ull r = fma2(n6h, mul2(zj[2], zj[6]), zj[12]);
        r = fma2(C, mul2(zj[2], p22), r);
        hj[12] = mul2(sv, r);
    }

    if (!LAST) {
        #pragma unroll
        for (int c = 0; c < 6; c++)
            reinterpret_cast<ulonglong2*>(B)[c] = make_ulonglong2(hj[2 * c], hj[2 * c + 1]);
        B[12] = hj[12];
    } else {
        // slot q==0: hj[j] = (psi_j, pressure_j) of point p
        const int pt = wbase + p;
        if (pt < n) {
            float ps[13], pp0 = 0.f, pp1 = 0.f, pp2 = 0.f;
            #pragma unroll
            for (int j = 0; j < 13; j++) {
                float a, b; unpack2(hj[j], a, b);
                ps[j] = a;
                if (j == 0) pp0 = b;
                else if (j == 1) pp1 = b;
                else if (j == 2) pp2 = b;
            }
            float u    =  ps[2];
            float v    = -ps[1];
            float p_x  =  pp1;
            float p_y  =  pp2;
            float u_t  =  ps[8];
            float u_x  =  ps[5];
            float u_y  =  ps[6];
            float v_t  = -ps[7];
            float v_x  = -ps[4];
            float v_y  = -ps[5];
            float u_xx =  ps[10];
            float u_yy =  ps[12];
            float v_xx = -ps[9];
            float v_yy = -ps[11];
            float f_u = u_t + l1 * (u * u_x + v * u_y) + p_x - l2 * (u_xx + u_yy);
            float f_v = v_t + l1 * (u * v_x + v * v_y) + p_y - l2 * (v_xx + v_yy);
            out[0 * n + pt] = u;
            out[1 * n + pt] = v;
            out[2 * n + pt] = pp0;
            out[3 * n + pt] = f_u;
            out[4 * n + pt] = f_v;
        }
    }
}

template <int DIN, int NQ, bool LAST>
__device__ __forceinline__ void layer(
    float (&ha)[20], int woff, int boff,
    ull* __restrict__ Sw, int g, int l16, int lane, int q1, int p1, bool isj0,
    float* __restrict__ out, int n, int wbase, float l1, float l2)
{
    constexpr int DOUTP = NQ * 2;
    constexpr int NC2 = NQ / 2;   // float4 chunks (4 units each)
    static_assert(NQ % 2 == 0, "NQ even");

    ull za[NQ];
    #pragma unroll
    for (int c = 0; c < NC2; c++) {
        const float4 b4 = *reinterpret_cast<const float4*>(&c_b[boff + 4 * c]);
        za[2 * c]     = isj0 ? pack2(b4.x, b4.y) : 0ull;
        za[2 * c + 1] = isj0 ? pack2(b4.z, b4.w) : 0ull;
    }
    #pragma unroll
    for (int i = 0; i < DIN; i++) {
        ull sa = pack2(ha[i], ha[i]);
        #pragma unroll
        for (int c = 0; c < NC2; c++) {
            const float4 w = *reinterpret_cast<const float4*>(&c_W[woff + i * DOUTP + 4 * c]);
            za[2 * c]     = fma2(sa, pack2(w.x, w.y), za[2 * c]);
            za[2 * c + 1] = fma2(sa, pack2(w.z, w.w), za[2 * c + 1]);
        }
    }

    __syncwarp();   // prior readers done before slots overwritten
    if (l16 < 13) {
        #pragma unroll
        for (int q = 0; q < NQ; q++)
            Sw[(g * 10 + q) * SLOT + l16] = za[q];
    }
    __syncwarp();   // z staged

    if (lane < 20 && q1 < NQ && (!LAST || q1 == 0))
        itemB<LAST>(Sw, lane, p1, out, n, wbase, l1, l2);
    __syncwarp();   // h staged

    if (!LAST && l16 < 13) {
        #pragma unroll
        for (int q = 0; q < NQ; q++)
            unpack2(Sw[(g * 10 + q) * SLOT + l16], ha[2 * q], ha[2 * q + 1]);
    }
}

__global__ void __launch_bounds__(NTHREADS, 3)
pinn_kernel(const float* __restrict__ X,
            const float* __restrict__ lam1p, const float* __restrict__ lam2p,
            float* __restrict__ out, int n)
{
    __shared__ __align__(16) ull Ssh[8 * WSW];

    const int tid  = threadIdx.x;
    const int warp = tid >> 5;
    const int lane = tid & 31;
    const int g    = lane >> 4;    // point within warp (0,1)
    const int l16  = lane & 15;    // jet (13..15 idle)
    const int q1   = lane % 10;    // phase-B unit-pair
    const int p1   = lane / 10;    // phase-B point (lanes 0..19)
    const bool isj0 = (l16 == 0);
    ull* Sw = Ssh + warp * WSW;

    // fold lb/ub partials (uniform, broadcast)
    unsigned mn = 0xFFFFFFFFu, mx = 0u;
    #pragma unroll
    for (int i = 0; i < GPART; i++) {
        mn = min(mn, g_pmin[i]);
        mx = max(mx, g_pmax[i]);
    }
    const float lb = dec_f(mn);
    const float ub = dec_f(mx);
    const float sc = 2.0f / (ub - lb);
    const float l1 = lam1p[0];
    const float l2 = lam2p[0];

    const int wbase = (blockIdx.x * 8 + warp) * 2;   // 2 points per warp
    const int cA = min(wbase + g, n - 1);

    float ha[20];
    #pragma unroll
    for (int k = 0; k < 20; k++) ha[k] = 0.0f;
    if (isj0) {
        ha[0] = sc * (X[3 * cA + 0] - lb) - 1.0f;
        ha[1] = sc * (X[3 * cA + 1] - lb) - 1.0f;
        ha[2] = sc * (X[3 * cA + 2] - lb) - 1.0f;
    } else if (l16 == 1) ha[0] = sc;
    else if (l16 == 2)   ha[1] = sc;
    else if (l16 == 3)   ha[2] = sc;

    layer<3, 2, false> (ha, 0,  0,  Sw, g, l16, lane, q1, p1, isj0, out, n, wbase, l1, l2);
    layer<3, 10, false>(ha, 12, 4,  Sw, g, l16, lane, q1, p1, isj0, out, n, wbase, l1, l2);
    #pragma unroll 1
    for (int l = 0; l < 5; l++) {
        layer<20, 10, false>(ha, 72 + 400 * l, 24 + 20 * l,
                             Sw, g, l16, lane, q1, p1, isj0, out, n, wbase, l1, l2);
    }
    layer<20, 2, true>(ha, 2072, 124, Sw, g, l16, lane, q1, p1, isj0, out, n, wbase, l1, l2);
}

extern "C" void kernel_launch(void* const* d_in, const int* in_sizes, int n_in,
                              void* d_out, int out_size) {
    const float* X    = (const float*)d_in[0];
    const float* W1   = (const float*)d_in[1];
    const float* b1   = (const float*)d_in[2];
    const float* W2   = (const float*)d_in[3];
    const float* b2   = (const float*)d_in[4];
    const float* W3   = (const float*)d_in[5];
    const float* b3   = (const float*)d_in[6];
    const float* W4   = (const float*)d_in[7];
    const float* b4   = (const float*)d_in[8];
    const float* W5   = (const float*)d_in[9];
    const float* b5   = (const float*)d_in[10];
    const float* W6   = (const float*)d_in[11];
    const float* b6   = (const float*)d_in[12];
    const float* W7   = (const float*)d_in[13];
    const float* b7   = (const float*)d_in[14];
    const float* W8   = (const float*)d_in[15];
    const float* b8   = (const float*)d_in[16];
    const float* lam1 = (const float*)d_in[17];
    const float* lam2 = (const float*)d_in[18];
    float* out = (float*)d_out;

    int n = in_sizes[0] / 3;

    k_repack<<<1, NTHREADS>>>(W1, b1, W2, b2, W3, b3, W4, b4,
                              W5, b5, W6, b6, W7, b7, W8, b8);
    void* wsrc = nullptr; void* bsrc = nullptr;
    cudaGetSymbolAddress(&wsrc, g_wst);
    cudaGetSymbolAddress(&bsrc, g_bst);
    cudaMemcpyToSymbolAsync(c_W, wsrc, WTOT * sizeof(float), 0, cudaMemcpyDeviceToDevice);
    cudaMemcpyToSymbolAsync(c_b, bsrc, BTOT * sizeof(float), 0, cudaMemcpyDeviceToDevice);

    k_partial_minmax<<<GPART, 256>>>(X, n);
    k_nop<<<1, 32>>>();   // aligns ncu -s 5 onto pinn_kernel

    int blocks = (n + 15) / 16;   // 16 points per block
    pinn_kernel<<<blocks, NTHREADS>>>(X, lam1, lam2, out, n);
}

// round 13
// speedup vs baseline: 1.2353x; 1.2353x over previous
#include <cuda_runtime.h>

typedef unsigned long long ull;

#define NTHREADS 256
#define GPART 32

#define WTOT 2152
#define BTOT 128
__constant__ float c_W[WTOT];
__constant__ float c_b[BTOT];
__device__ float g_wst[WTOT];
__device__ float g_bst[BTOT];

#define SLOT 18     // u64 stride per (point, unit-pair) slot  (144 B)
#define WSW  720    // per-warp smem in u64 (40 slots * 18)

// ---------------- packed f32x2 helpers (sm_103a) ----------------
__device__ __forceinline__ ull fma2(ull a, ull b, ull c) {
    ull d; asm("fma.rn.f32x2 %0,%1,%2,%3;" : "=l"(d) : "l"(a), "l"(b), "l"(c)); return d;
}
__device__ __forceinline__ ull mul2(ull a, ull b) {
    ull d; asm("mul.rn.f32x2 %0,%1,%2;" : "=l"(d) : "l"(a), "l"(b)); return d;
}
__device__ __forceinline__ ull pack2(float lo, float hi) {
    ull d; asm("mov.b64 %0,{%1,%2};" : "=l"(d) : "f"(lo), "f"(hi)); return d;
}
__device__ __forceinline__ void unpack2(ull v, float& lo, float& hi) {
    asm("mov.b64 {%0,%1},%2;" : "=f"(lo), "=f"(hi) : "l"(v));
}
__device__ __forceinline__ float tanh_fast(float x) {
    float y; asm("tanh.approx.f32 %0, %1;" : "=f"(y) : "f"(x));
    return y;
}

#define ONE2     0x3F8000003F800000ull
#define NEGONE2  0xBF800000BF800000ull
#define NEGTWO2  0xC0000000C0000000ull
#define SIX2     0x40C0000040C00000ull
#define NEGFOUR2 0xC0800000C0800000ull
#define NEGSIX2  0xC0C00000C0C00000ull

// ---------------- lb/ub reduction ----------------
__device__ unsigned g_pmin[GPART];
__device__ unsigned g_pmax[GPART];

__device__ __forceinline__ unsigned enc_f(float f) {
    unsigned u = __float_as_uint(f);
    return (u & 0x80000000u) ? ~u : (u | 0x80000000u);
}
__device__ __forceinline__ float dec_f(unsigned e) {
    unsigned u = (e & 0x80000000u) ? (e ^ 0x80000000u) : ~e;
    return __uint_as_float(u);
}

__global__ void k_partial_minmax(const float* __restrict__ X, int n) {
    __shared__ unsigned smn[8], smx[8];
    unsigned mn = 0xFFFFFFFFu, mx = 0u;
    for (int i = blockIdx.x * blockDim.x + threadIdx.x; i < n;
         i += gridDim.x * blockDim.x) {
        unsigned e = enc_f(X[3 * i]);
        mn = min(mn, e); mx = max(mx, e);
    }
    #pragma unroll
    for (int o = 16; o; o >>= 1) {
        mn = min(mn, __shfl_xor_sync(0xffffffffu, mn, o));
        mx = max(mx, __shfl_xor_sync(0xffffffffu, mx, o));
    }
    int w = threadIdx.x >> 5;
    if ((threadIdx.x & 31) == 0) { smn[w] = mn; smx[w] = mx; }
    __syncthreads();
    if (threadIdx.x == 0) {
        #pragma unroll
        for (int i = 1; i < 8; i++) { mn = min(mn, smn[i]); mx = max(mx, smx[i]); }
        g_pmin[blockIdx.x] = mn;
        g_pmax[blockIdx.x] = mx;
    }
}

__global__ void k_nop() {}   // stream-slot filler so ncu -s 5 lands on pinn_kernel

// repack weights into padded float layout in __device__ staging
__global__ void k_repack(const float* __restrict__ W1, const float* __restrict__ b1,
                         const float* __restrict__ W2, const float* __restrict__ b2,
                         const float* __restrict__ W3, const float* __restrict__ b3,
                         const float* __restrict__ W4, const float* __restrict__ b4,
                         const float* __restrict__ W5, const float* __restrict__ b5,
                         const float* __restrict__ W6, const float* __restrict__ b6,
                         const float* __restrict__ W7, const float* __restrict__ b7,
                         const float* __restrict__ W8, const float* __restrict__ b8) {
    const int WOFF[8] = {0, 12, 72, 472, 872, 1272, 1672, 2072};
    const int LDIN[8] = {3, 3, 20, 20, 20, 20, 20, 20};
    const int DSRC[8] = {3, 20, 20, 20, 20, 20, 20, 2};
    const int DPAD[8] = {4, 20, 20, 20, 20, 20, 20, 4};
    const int BOFF[8] = {0, 4, 24, 44, 64, 84, 104, 124};
    const float* Wg[8] = {W1, W2, W3, W4, W5, W6, W7, W8};
    const float* Bg[8] = {b1, b2, b3, b4, b5, b6, b7, b8};
    int tid = threadIdx.x;
    #pragma unroll
    for (int l = 0; l < 8; l++) {
        int tot = LDIN[l] * DPAD[l];
        for (int i = tid; i < tot; i += NTHREADS) {
            int r = i / DPAD[l], c = i % DPAD[l];
            g_wst[WOFF[l] + i] = (c < DSRC[l]) ? Wg[l][r * DSRC[l] + c] : 0.0f;
        }
        for (int i = tid; i < DPAD[l]; i += NTHREADS)
            g_bst[BOFF[l] + i] = (i < DSRC[l]) ? Bg[l][i] : 0.0f;
    }
}

// Jet order: 0:val 1:x 2:y 3:t 4:xx 5:xy 6:yy 7:xt 8:yt 9:xxx 10:xxy 11:xyy 12:yyy
// Per-warp smem: 40 slots (4 points x 10 unit-pairs), slot w at Sw[w*18 .. w*18+12]

template <bool LAST>
__device__ __forceinline__ void itemB(ull* __restrict__ Sw, int w, int p,
                                      float* __restrict__ out, int n, int wbase,
                                      float l1, float l2)
{
    ull* B = Sw + w * SLOT;
    ull zj[13];
    #pragma unroll
    for (int c = 0; c < 6; c++) {
        ulonglong2 v = reinterpret_cast<const ulonglong2*>(B)[c];
        zj[2 * c] = v.x; zj[2 * c + 1] = v.y;
    }
    zj[12] = B[12];

    float t0, t1; unpack2(zj[0], t0, t1);
    ull t   = pack2(tanh_fast(t0), tanh_fast(t1));
    ull hq  = mul2(t, t);
    ull sv  = fma2(hq, NEGONE2, ONE2);     // s = 1 - t^2
    ull C   = fma2(hq, SIX2, NEGTWO2);     // 6t^2 - 2
    ull n2h = mul2(t, NEGTWO2);
    ull n4h = mul2(t, NEGFOUR2);
    ull n6h = mul2(t, NEGSIX2);
    ull p11 = mul2(zj[1], zj[1]);
    ull p12 = mul2(zj[1], zj[2]);
    ull p22 = mul2(zj[2], zj[2]);
    ull p13 = mul2(zj[1], zj[3]);
    ull p23 = mul2(zj[2], zj[3]);

    ull hj[13];
    hj[0] = t;
    hj[1] = mul2(sv, zj[1]);
    hj[2] = mul2(sv, zj[2]);
    hj[3] = mul2(sv, zj[3]);
    hj[4] = mul2(sv, fma2(n2h, p11, zj[4]));
    hj[5] = mul2(sv, fma2(n2h, p12, zj[5]));
    hj[6] = mul2(sv, fma2(n2h, p22, zj[6]));
    hj[7] = mul2(sv, fma2(n2h, p13, zj[7]));
    hj[8] = mul2(sv, fma2(n2h, p23, zj[8]));
    {   // xxx
        ull r = fma2(n6h, mul2(zj[1], zj[4]), zj[9]);
        r = fma2(C, mul2(zj[1], p11), r);
        hj[9] = mul2(sv, r);
    }
    {   // xxy
        ull r = fma2(n2h, mul2(zj[2], zj[4]), zj[10]);
        r = fma2(n4h, mul2(zj[1], zj[5]), r);
        r = fma2(C, mul2(p11, zj[2]), r);
        hj[10] = mul2(sv, r);
    }
    {   // xyy
        ull r = fma2(n4h, mul2(zj[2], zj[5]), zj[11]);
        r = fma2(n2h, mul2(zj[1], zj[6]), r);
        r = fma2(C, mul2(zj[1], p22), r);
        hj[11] = mul2(sv, r);
    }
    {   // yyy
        ull r = fma2(n6h, mul2(zj[2], zj[6]), zj[12]);
        r = fma2(C, mul2(zj[2], p22), r);
        hj[12] = mul2(sv, r);
    }

    if (!LAST) {
        #pragma unroll
        for (int c = 0; c < 6; c++)
            reinterpret_cast<ulonglong2*>(B)[c] = make_ulonglong2(hj[2 * c], hj[2 * c + 1]);
        B[12] = hj[12];
    } else {
        // slot q==0: hj[j] = (psi_j, pressure_j) of point p
        const int pt = wbase + p;
        if (pt < n) {
            float ps[13], pp0 = 0.f, pp1 = 0.f, pp2 = 0.f;
            #pragma unroll
            for (int j = 0; j < 13; j++) {
                float a, b; unpack2(hj[j], a, b);
                ps[j] = a;
                if (j == 0) pp0 = b;
                else if (j == 1) pp1 = b;
                else if (j == 2) pp2 = b;
            }
            float u    =  ps[2];
            float v    = -ps[1];
            float p_x  =  pp1;
            float p_y  =  pp2;
            float u_t  =  ps[8];
            float u_x  =  ps[5];
            float u_y  =  ps[6];
            float v_t  = -ps[7];
            float v_x  = -ps[4];
            float v_y  = -ps[5];
            float u_xx =  ps[10];
            float u_yy =  ps[12];
            float v_xx = -ps[9];
            float v_yy = -ps[11];
            float f_u = u_t + l1 * (u * u_x + v * u_y) + p_x - l2 * (u_xx + u_yy);
            float f_v = v_t + l1 * (u * v_x + v * v_y) + p_y - l2 * (v_xx + v_yy);
            out[0 * n + pt] = u;
            out[1 * n + pt] = v;
            out[2 * n + pt] = pp0;
            out[3 * n + pt] = f_u;
            out[4 * n + pt] = f_v;
        }
    }
}

template <int DIN, int NQ, bool LAST>
__device__ __forceinline__ void layer(
    float (&ha)[20], float (&hb)[20], int woff, int boff,
    ull* __restrict__ Sw, int g, int l16, int lane, int q1, int p1, bool isj0,
    float* __restrict__ out, int n, int wbase, float l1, float l2)
{
    constexpr int DOUTP = NQ * 2;
    constexpr int NC2 = NQ / 2;   // ulonglong2 chunks (4 units each)
    static_assert(NQ % 2 == 0, "NQ even");

    ull za[NQ], zb[NQ];
    #pragma unroll
    for (int c = 0; c < NC2; c++) {
        // direct 16B constant load; u64 halves are already f32x2-packed (b0,b1)
        const ulonglong2 b2v = *reinterpret_cast<const ulonglong2*>(&c_b[boff + 4 * c]);
        za[2 * c]     = isj0 ? b2v.x : 0ull;
        za[2 * c + 1] = isj0 ? b2v.y : 0ull;
        zb[2 * c]     = za[2 * c];
        zb[2 * c + 1] = za[2 * c + 1];
    }
    #pragma unroll
    for (int i = 0; i < DIN; i++) {
        ull sa = pack2(ha[i], ha[i]);
        ull sb = pack2(hb[i], hb[i]);
        #pragma unroll
        for (int c = 0; c < NC2; c++) {
            // direct 16B constant load: w.x = (w0,w1), w.y = (w2,w3) — no repacking
            const ulonglong2 w = *reinterpret_cast<const ulonglong2*>(&c_W[woff + i * DOUTP + 4 * c]);
            za[2 * c]     = fma2(sa, w.x, za[2 * c]);
            za[2 * c + 1] = fma2(sa, w.y, za[2 * c + 1]);
            zb[2 * c]     = fma2(sb, w.x, zb[2 * c]);
            zb[2 * c + 1] = fma2(sb, w.y, zb[2 * c + 1]);
        }
    }

    __syncwarp();   // prior readers done before slots overwritten
    if (l16 < 13) {
        #pragma unroll
        for (int q = 0; q < NQ; q++) {
            Sw[((g * 2 + 0) * 10 + q) * SLOT + l16] = za[q];
            Sw[((g * 2 + 1) * 10 + q) * SLOT + l16] = zb[q];
        }
    }
    __syncwarp();   // z staged

    if (q1 < NQ && (!LAST || q1 == 0))
        itemB<LAST>(Sw, lane, p1, out, n, wbase, l1, l2);
    if (!LAST && lane < 8 && (lane + 2) < NQ)
        itemB<false>(Sw, lane + 32, 0, out, n, wbase, l1, l2);
    __syncwarp();   // h staged

    if (!LAST && l16 < 13) {
        #pragma unroll
        for (int q = 0; q < NQ; q++) {
            unpack2(Sw[((g * 2 + 0) * 10 + q) * SLOT + l16], ha[2 * q], ha[2 * q + 1]);
            unpack2(Sw[((g * 2 + 1) * 10 + q) * SLOT + l16], hb[2 * q], hb[2 * q + 1]);
        }
    }
}

__global__ void __launch_bounds__(NTHREADS, 2)
pinn_kernel(const float* __restrict__ X,
            const float* __restrict__ lam1p, const float* __restrict__ lam2p,
            float* __restrict__ out, int n)
{
    __shared__ __align__(16) ull Ssh[8 * WSW];

    const int tid  = threadIdx.x;
    const int warp = tid >> 5;
    const int lane = tid & 31;
    const int g    = lane >> 4;
    const int l16  = lane & 15;
    const int q1   = lane % 10;
    const int p1   = lane / 10;
    const bool isj0 = (l16 == 0);
    ull* Sw = Ssh + warp * WSW;

    // fold lb/ub partials (uniform, broadcast)
    unsigned mn = 0xFFFFFFFFu, mx = 0u;
    #pragma unroll
    for (int i = 0; i < GPART; i++) {
        mn = min(mn, g_pmin[i]);
        mx = max(mx, g_pmax[i]);
    }
    const float lb = dec_f(mn);
    const float ub = dec_f(mx);
    const float sc = 2.0f / (ub - lb);
    const float l1 = lam1p[0];
    const float l2 = lam2p[0];

    const int wbase = (blockIdx.x * 8 + warp) * 4;   // 4 points per warp
    const int cA = min(wbase + g * 2,     n - 1);
    const int cB = min(wbase + g * 2 + 1, n - 1);

    float ha[20], hb[20];
    #pragma unroll
    for (int k = 0; k < 20; k++) { ha[k] = 0.0f; hb[k] = 0.0f; }
    if (isj0) {
        ha[0] = sc * (X[3 * cA + 0] - lb) - 1.0f;
        ha[1] = sc * (X[3 * cA + 1] - lb) - 1.0f;
        ha[2] = sc * (X[3 * cA + 2] - lb) - 1.0f;
        hb[0] = sc * (X[3 * cB + 0] - lb) - 1.0f;
        hb[1] = sc * (X[3 * cB + 1] - lb) - 1.0f;
        hb[2] = sc * (X[3 * cB + 2] - lb) - 1.0f;
    } else if (l16 == 1) { ha[0] = sc; hb[0] = sc; }
    else if (l16 == 2)   { ha[1] = sc; hb[1] = sc; }
    else if (l16 == 3)   { ha[2] = sc; hb[2] = sc; }

    layer<3, 2, false> (ha, hb, 0,  0,  Sw, g, l16, lane, q1, p1, isj0, out, n, wbase, l1, l2);
    layer<3, 10, false>(ha, hb, 12, 4,  Sw, g, l16, lane, q1, p1, isj0, out, n, wbase, l1, l2);
    #pragma unroll 1
    for (int l = 0; l < 5; l++) {
        layer<20, 10, false>(ha, hb, 72 + 400 * l, 24 + 20 * l,
                             Sw, g, l16, lane, q1, p1, isj0, out, n, wbase, l1, l2);
    }
    layer<20, 2, true>(ha, hb, 2072, 124, Sw, g, l16, lane, q1, p1, isj0, out, n, wbase, l1, l2);
}

extern "C" void kernel_launch(void* const* d_in, const int* in_sizes, int n_in,
                              void* d_out, int out_size) {
    const float* X    = (const float*)d_in[0];
    const float* W1   = (const float*)d_in[1];
    const float* b1   = (const float*)d_in[2];
    const float* W2   = (const float*)d_in[3];
    const float* b2   = (const float*)d_in[4];
    const float* W3   = (const float*)d_in[5];
    const float* b3   = (const float*)d_in[6];
    const float* W4   = (const float*)d_in[7];
    const float* b4   = (const float*)d_in[8];
    const float* W5   = (const float*)d_in[9];
    const float* b5   = (const float*)d_in[10];
    const float* W6   = (const float*)d_in[11];
    const float* b6   = (const float*)d_in[12];
    const float* W7   = (const float*)d_in[13];
    const float* b7   = (const float*)d_in[14];
    const float* W8   = (const float*)d_in[15];
    const float* b8   = (const float*)d_in[16];
    const float* lam1 = (const float*)d_in[17];
    const float* lam2 = (const float*)d_in[18];
    float* out = (float*)d_out;

    int n = in_sizes[0] / 3;

    k_repack<<<1, NTHREADS>>>(W1, b1, W2, b2, W3, b3, W4, b4,
                              W5, b5, W6, b6, W7, b7, W8, b8);
    void* wsrc = nullptr; void* bsrc = nullptr;
    cudaGetSymbolAddress(&wsrc, g_wst);
    cudaGetSymbolAddress(&bsrc, g_bst);
    cudaMemcpyToSymbolAsync(c_W, wsrc, WTOT * sizeof(float), 0, cudaMemcpyDeviceToDevice);
    cudaMemcpyToSymbolAsync(c_b, bsrc, BTOT * sizeof(float), 0, cudaMemcpyDeviceToDevice);

    k_partial_minmax<<<GPART, 256>>>(X, n);
    k_nop<<<1, 32>>>();   // aligns ncu -s 5 onto pinn_kernel

    int blocks = (n + 31) / 32;   // 32 points per block
    pinn_kernel<<<blocks, NTHREADS>>>(X, lam1, lam2, out, n);
}

// round 14
// speedup vs baseline: 1.3012x; 1.0534x over previous
#include <cuda_runtime.h>

typedef unsigned long long ull;

#define NTHREADS 256
#define GPART 32

#define WTOT 2176
#define BTOT 128
__constant__ float c_W[WTOT];
__constant__ float c_b[BTOT];
__device__ float g_wst[WTOT];
__device__ float g_bst[BTOT];

#define SLOT 18     // u64 stride per (point, unit-pair) slot  (144 B)
#define WSW  720    // per-warp smem in u64 (40 slots * 18)

// ---------------- packed f32x2 helpers (sm_103a) ----------------
__device__ __forceinline__ ull fma2(ull a, ull b, ull c) {
    ull d; asm("fma.rn.f32x2 %0,%1,%2,%3;" : "=l"(d) : "l"(a), "l"(b), "l"(c)); return d;
}
__device__ __forceinline__ ull mul2(ull a, ull b) {
    ull d; asm("mul.rn.f32x2 %0,%1,%2;" : "=l"(d) : "l"(a), "l"(b)); return d;
}
__device__ __forceinline__ ull pack2(float lo, float hi) {
    ull d; asm("mov.b64 %0,{%1,%2};" : "=l"(d) : "f"(lo), "f"(hi)); return d;
}
__device__ __forceinline__ void unpack2(ull v, float& lo, float& hi) {
    asm("mov.b64 {%0,%1},%2;" : "=f"(lo), "=f"(hi) : "l"(v));
}
__device__ __forceinline__ float tanh_fast(float x) {
    float y; asm("tanh.approx.f32 %0, %1;" : "=f"(y) : "f"(x));
    return y;
}

#define ONE2     0x3F8000003F800000ull
#define NEGONE2  0xBF800000BF800000ull
#define NEGTWO2  0xC0000000C0000000ull
#define SIX2     0x40C0000040C00000ull
#define NEGFOUR2 0xC0800000C0800000ull
#define NEGSIX2  0xC0C00000C0C00000ull

// ---------------- lb/ub reduction ----------------
__device__ unsigned g_pmin[GPART];
__device__ unsigned g_pmax[GPART];

__device__ __forceinline__ unsigned enc_f(float f) {
    unsigned u = __float_as_uint(f);
    return (u & 0x80000000u) ? ~u : (u | 0x80000000u);
}
__device__ __forceinline__ float dec_f(unsigned e) {
    unsigned u = (e & 0x80000000u) ? (e ^ 0x80000000u) : ~e;
    return __uint_as_float(u);
}

__global__ void k_partial_minmax(const float* __restrict__ X, int n) {
    __shared__ unsigned smn[8], smx[8];
    unsigned mn = 0xFFFFFFFFu, mx = 0u;
    for (int i = blockIdx.x * blockDim.x + threadIdx.x; i < n;
         i += gridDim.x * blockDim.x) {
        unsigned e = enc_f(X[3 * i]);
        mn = min(mn, e); mx = max(mx, e);
    }
    #pragma unroll
    for (int o = 16; o; o >>= 1) {
        mn = min(mn, __shfl_xor_sync(0xffffffffu, mn, o));
        mx = max(mx, __shfl_xor_sync(0xffffffffu, mx, o));
    }
    int w = threadIdx.x >> 5;
    if ((threadIdx.x & 31) == 0) { smn[w] = mn; smx[w] = mx; }
    __syncthreads();
    if (threadIdx.x == 0) {
        #pragma unroll
        for (int i = 1; i < 8; i++) { mn = min(mn, smn[i]); mx = max(mx, smx[i]); }
        g_pmin[blockIdx.x] = mn;
        g_pmax[blockIdx.x] = mx;
    }
}

__global__ void k_nop() {}   // stream-slot filler so ncu -s 5 lands on pinn_kernel

// repack weights: rows of layers 1-2 padded 3->4, cols padded per table
__global__ void k_repack(const float* __restrict__ W1, const float* __restrict__ b1,
                         const float* __restrict__ W2, const float* __restrict__ b2,
                         const float* __restrict__ W3, const float* __restrict__ b3,
                         const float* __restrict__ W4, const float* __restrict__ b4,
                         const float* __restrict__ W5, const float* __restrict__ b5,
                         const float* __restrict__ W6, const float* __restrict__ b6,
                         const float* __restrict__ W7, const float* __restrict__ b7,
                         const float* __restrict__ W8, const float* __restrict__ b8) {
    const int WOFF[8] = {0, 16, 96, 496, 896, 1296, 1696, 2096};
    const int RPAD[8] = {4, 4, 20, 20, 20, 20, 20, 20};
    const int RSRC[8] = {3, 3, 20, 20, 20, 20, 20, 20};
    const int CPAD[8] = {4, 20, 20, 20, 20, 20, 20, 4};
    const int CSRC[8] = {3, 20, 20, 20, 20, 20, 20, 2};
    const int BOFF[8] = {0, 4, 24, 44, 64, 84, 104, 124};
    const float* Wg[8] = {W1, W2, W3, W4, W5, W6, W7, W8};
    const float* Bg[8] = {b1, b2, b3, b4, b5, b6, b7, b8};
    int tid = threadIdx.x;
    #pragma unroll
    for (int l = 0; l < 8; l++) {
        int tot = RPAD[l] * CPAD[l];
        for (int i = tid; i < tot; i += NTHREADS) {
            int r = i / CPAD[l], c = i % CPAD[l];
            g_wst[WOFF[l] + i] = (r < RSRC[l] && c < CSRC[l]) ? Wg[l][r * CSRC[l] + c] : 0.0f;
        }
        for (int i = tid; i < CPAD[l]; i += NTHREADS)
            g_bst[BOFF[l] + i] = (i < CSRC[l]) ? Bg[l][i] : 0.0f;
    }
}

// Jet order: 0:val 1:x 2:y 3:t 4:xx 5:xy 6:yy 7:xt 8:yt 9:xxx 10:xxy 11:xyy 12:yyy
// Per-warp smem: 40 slots (4 points x 10 unit-pairs), slot w at Sw[w*18 .. w*18+12]
// Slot word j = (h_or_z[2q], h_or_z[2q+1]) of jet j for that (point, unit-pair).

template <bool LAST>
__device__ __forceinline__ void itemB(ull* __restrict__ Sw, int w, int p,
                                      float* __restrict__ out, int n, int wbase,
                                      float l1, float l2)
{
    ull* B = Sw + w * SLOT;
    ull zj[13];
    #pragma unroll
    for (int c = 0; c < 6; c++) {
        ulonglong2 v = reinterpret_cast<const ulonglong2*>(B)[c];
        zj[2 * c] = v.x; zj[2 * c + 1] = v.y;
    }
    zj[12] = B[12];

    float t0, t1; unpack2(zj[0], t0, t1);
    ull t   = pack2(tanh_fast(t0), tanh_fast(t1));
    ull hq  = mul2(t, t);
    ull sv  = fma2(hq, NEGONE2, ONE2);     // s = 1 - t^2
    ull C   = fma2(hq, SIX2, NEGTWO2);     // 6t^2 - 2
    ull n2h = mul2(t, NEGTWO2);
    ull n4h = mul2(t, NEGFOUR2);
    ull n6h = mul2(t, NEGSIX2);
    ull p11 = mul2(zj[1], zj[1]);
    ull p12 = mul2(zj[1], zj[2]);
    ull p22 = mul2(zj[2], zj[2]);
    ull p13 = mul2(zj[1], zj[3]);
    ull p23 = mul2(zj[2], zj[3]);

    ull hj[13];
    hj[0] = t;
    hj[1] = mul2(sv, zj[1]);
    hj[2] = mul2(sv, zj[2]);
    hj[3] = mul2(sv, zj[3]);
    hj[4] = mul2(sv, fma2(n2h, p11, zj[4]));
    hj[5] = mul2(sv, fma2(n2h, p12, zj[5]));
    hj[6] = mul2(sv, fma2(n2h, p22, zj[6]));
    hj[7] = mul2(sv, fma2(n2h, p13, zj[7]));
    hj[8] = mul2(sv, fma2(n2h, p23, zj[8]));
    {   // xxx
        ull r = fma2(n6h, mul2(zj[1], zj[4]), zj[9]);
        r = fma2(C, mul2(zj[1], p11), r);
        hj[9] = mul2(sv, r);
    }
    {   // xxy
        ull r = fma2(n2h, mul2(zj[2], zj[4]), zj[10]);
        r = fma2(n4h, mul2(zj[1], zj[5]), r);
        r = fma2(C, mul2(p11, zj[2]), r);
        hj[10] = mul2(sv, r);
    }
    {   // xyy
        ull r = fma2(n4h, mul2(zj[2], zj[5]), zj[11]);
        r = fma2(n2h, mul2(zj[1], zj[6]), r);
        r = fma2(C, mul2(zj[1], p22), r);
        hj[11] = mul2(sv, r);
    }
    {   // yyy
        ull r = fma2(n6h, mul2(zj[2], zj[6]), zj[12]);
        r = fma2(C, mul2(zj[2], p22), r);
        hj[12] = mul2(sv, r);
    }

    if (!LAST) {
        #pragma unroll
        for (int c = 0; c < 6; c++)
            reinterpret_cast<ulonglong2*>(B)[c] = make_ulonglong2(hj[2 * c], hj[2 * c + 1]);
        B[12] = hj[12];
    } else {
        const int pt = wbase + p;
        if (pt < n) {
            float ps[13], pp0 = 0.f, pp1 = 0.f, pp2 = 0.f;
            #pragma unroll
            for (int j = 0; j < 13; j++) {
                float a, b; unpack2(hj[j], a, b);
                ps[j] = a;
                if (j == 0) pp0 = b;
                else if (j == 1) pp1 = b;
                else if (j == 2) pp2 = b;
            }
            float u    =  ps[2];
            float v    = -ps[1];
            float p_x  =  pp1;
            float p_y  =  pp2;
            float u_t  =  ps[8];
            float u_x  =  ps[5];
            float u_y  =  ps[6];
            float v_t  = -ps[7];
            float v_x  = -ps[4];
            float v_y  = -ps[5];
            float u_xx =  ps[10];
            float u_yy =  ps[12];
            float v_xx = -ps[9];
            float v_yy = -ps[11];
            float f_u = u_t + l1 * (u * u_x + v * u_y) + p_x - l2 * (u_xx + u_yy);
            float f_v = v_t + l1 * (u * v_x + v * v_y) + p_y - l2 * (v_xx + v_yy);
            out[0 * n + pt] = u;
            out[1 * n + pt] = v;
            out[2 * n + pt] = pp0;
            out[3 * n + pt] = f_u;
            out[4 * n + pt] = f_v;
        }
    }
}

// DINP2 = input unit-pairs (2 for padded-4 inputs, 10 for 20-wide)
template <int DINP2, int NQ, bool LAST>
__device__ __forceinline__ void layer(
    int woff, int boff,
    ull* __restrict__ Sw, int g, int l16, int lane, int q1, int p1, bool isj0,
    float* __restrict__ out, int n, int wbase, float l1, float l2)
{
    constexpr int DOUTP = NQ * 2;
    constexpr int NC2 = NQ / 2;   // ulonglong2 chunks (4 units each)
    static_assert(NQ % 2 == 0, "NQ even");

    ull za[NQ], zb[NQ];
    #pragma unroll
    for (int c = 0; c < NC2; c++) {
        const ulonglong2 b2v = *reinterpret_cast<const ulonglong2*>(&c_b[boff + 4 * c]);
        za[2 * c]     = isj0 ? b2v.x : 0ull;
        za[2 * c + 1] = isj0 ? b2v.y : 0ull;
        zb[2 * c]     = za[2 * c];
        zb[2 * c + 1] = za[2 * c + 1];
    }

    const int baseA = ((g * 2 + 0) * 10) * SLOT + l16;
    const int baseB = ((g * 2 + 1) * 10) * SLOT + l16;
    #pragma unroll
    for (int ip = 0; ip < DINP2; ip++) {
        const ull vA = Sw[baseA + ip * SLOT];   // (hA[2ip], hA[2ip+1])
        const ull vB = Sw[baseB + ip * SLOT];
        float a0, a1, b0, b1;
        unpack2(vA, a0, a1); unpack2(vB, b0, b1);
        const ull sa0 = pack2(a0, a0), sa1 = pack2(a1, a1);
        const ull sb0 = pack2(b0, b0), sb1 = pack2(b1, b1);
        #pragma unroll
        for (int c = 0; c < NC2; c++) {
            const ulonglong2 w0 = *reinterpret_cast<const ulonglong2*>(&c_W[woff + (2 * ip) * DOUTP + 4 * c]);
            const ulonglong2 w1 = *reinterpret_cast<const ulonglong2*>(&c_W[woff + (2 * ip + 1) * DOUTP + 4 * c]);
            za[2 * c]     = fma2(sa0, w0.x, za[2 * c]);
            za[2 * c + 1] = fma2(sa0, w0.y, za[2 * c + 1]);
            za[2 * c]     = fma2(sa1, w1.x, za[2 * c]);
            za[2 * c + 1] = fma2(sa1, w1.y, za[2 * c + 1]);
            zb[2 * c]     = fma2(sb0, w0.x, zb[2 * c]);
            zb[2 * c + 1] = fma2(sb0, w0.y, zb[2 * c + 1]);
            zb[2 * c]     = fma2(sb1, w1.x, zb[2 * c]);
            zb[2 * c + 1] = fma2(sb1, w1.y, zb[2 * c + 1]);
        }
    }

    __syncwarp();   // all h reads done before slots overwritten with z
    if (l16 < 13) {
        #pragma unroll
        for (int q = 0; q < NQ; q++) {
            Sw[((g * 2 + 0) * 10 + q) * SLOT + l16] = za[q];
            Sw[((g * 2 + 1) * 10 + q) * SLOT + l16] = zb[q];
        }
    }
    __syncwarp();   // z staged

    if (q1 < NQ && (!LAST || q1 == 0))
        itemB<LAST>(Sw, lane, p1, out, n, wbase, l1, l2);
    if (!LAST && lane < 8 && (lane + 2) < NQ)
        itemB<false>(Sw, lane + 32, 0, out, n, wbase, l1, l2);
    if (!LAST) __syncwarp();   // h staged for next layer's in-loop reads
}

__global__ void __launch_bounds__(NTHREADS, 3)
pinn_kernel(const float* __restrict__ X,
            const float* __restrict__ lam1p, const float* __restrict__ lam2p,
            float* __restrict__ out, int n)
{
    __shared__ __align__(16) ull Ssh[8 * WSW];

    const int tid  = threadIdx.x;
    const int warp = tid >> 5;
    const int lane = tid & 31;
    const int g    = lane >> 4;
    const int l16  = lane & 15;
    const int q1   = lane % 10;
    const int p1   = lane / 10;
    const bool isj0 = (l16 == 0);
    ull* Sw = Ssh + warp * WSW;

    // fold lb/ub partials (uniform, broadcast)
    unsigned mn = 0xFFFFFFFFu, mx = 0u;
    #pragma unroll
    for (int i = 0; i < GPART; i++) {
        mn = min(mn, g_pmin[i]);
        mx = max(mx, g_pmax[i]);
    }
    const float lb = dec_f(mn);
    const float ub = dec_f(mx);
    const float sc = 2.0f / (ub - lb);
    const float l1 = lam1p[0];
    const float l2 = lam2p[0];

    const int wbase = (blockIdx.x * 8 + warp) * 4;   // 4 points per warp
    const int cA = min(wbase + g * 2,     n - 1);
    const int cB = min(wbase + g * 2 + 1, n - 1);

    // stage the input-layer h jets into slots q=0,1 of both points
    if (l16 < 13) {
        float hA0 = 0.f, hA1 = 0.f, hA2 = 0.f, hB0 = 0.f, hB1 = 0.f, hB2 = 0.f;
        if (isj0) {
            hA0 = sc * (X[3 * cA + 0] - lb) - 1.0f;
            hA1 = sc * (X[3 * cA + 1] - lb) - 1.0f;
            hA2 = sc * (X[3 * cA + 2] - lb) - 1.0f;
            hB0 = sc * (X[3 * cB + 0] - lb) - 1.0f;
            hB1 = sc * (X[3 * cB + 1] - lb) - 1.0f;
            hB2 = sc * (X[3 * cB + 2] - lb) - 1.0f;
        } else if (l16 == 1) { hA0 = sc; hB0 = sc; }
        else if (l16 == 2)   { hA1 = sc; hB1 = sc; }
        else if (l16 == 3)   { hA2 = sc; hB2 = sc; }
        Sw[((g * 2 + 0) * 10 + 0) * SLOT + l16] = pack2(hA0, hA1);
        Sw[((g * 2 + 0) * 10 + 1) * SLOT + l16] = pack2(hA2, 0.0f);
        Sw[((g * 2 + 1) * 10 + 0) * SLOT + l16] = pack2(hB0, hB1);
        Sw[((g * 2 + 1) * 10 + 1) * SLOT + l16] = pack2(hB2, 0.0f);
    }
    __syncwarp();

    layer<2, 2, false> (0,    0,   Sw, g, l16, lane, q1, p1, isj0, out, n, wbase, l1, l2);
    layer<2, 10, false>(16,   4,   Sw, g, l16, lane, q1, p1, isj0, out, n, wbase, l1, l2);
    #pragma unroll 1
    for (int l = 0; l < 5; l++) {
        layer<10, 10, false>(96 + 400 * l, 24 + 20 * l,
                             Sw, g, l16, lane, q1, p1, isj0, out, n, wbase, l1, l2);
    }
    layer<10, 2, true>(2096, 124, Sw, g, l16, lane, q1, p1, isj0, out, n, wbase, l1, l2);
}

extern "C" void kernel_launch(void* const* d_in, const int* in_sizes, int n_in,
                              void* d_out, int out_size) {
    const float* X    = (const float*)d_in[0];
    const float* W1   = (const float*)d_in[1];
    const float* b1   = (const float*)d_in[2];
    const float* W2   = (const float*)d_in[3];
    const float* b2   = (const float*)d_in[4];
    const float* W3   = (const float*)d_in[5];
    const float* b3   = (const float*)d_in[6];
    const float* W4   = (const float*)d_in[7];
    const float* b4   = (const float*)d_in[8];
    const float* W5   = (const float*)d_in[9];
    const float* b5   = (const float*)d_in[10];
    const float* W6   = (const float*)d_in[11];
    const float* b6   = (const float*)d_in[12];
    const float* W7   = (const float*)d_in[13];
    const float* b7   = (const float*)d_in[14];
    const float* W8   = (const float*)d_in[15];
    const float* b8   = (const float*)d_in[16];
    const float* lam1 = (const float*)d_in[17];
    const float* lam2 = (const float*)d_in[18];
    float* out = (float*)d_out;

    int n = in_sizes[0] / 3;

    k_repack<<<1, NTHREADS>>>(W1, b1, W2, b2, W3, b3, W4, b4,
                              W5, b5, W6, b6, W7, b7, W8, b8);
    void* wsrc = nullptr; void* bsrc = nullptr;
    cudaGetSymbolAddress(&wsrc, g_wst);
    cudaGetSymbolAddress(&bsrc, g_bst);
    cudaMemcpyToSymbolAsync(c_W, wsrc, WTOT * sizeof(float), 0, cudaMemcpyDeviceToDevice);
    cudaMemcpyToSymbolAsync(c_b, bsrc, BTOT * sizeof(float), 0, cudaMemcpyDeviceToDevice);

    k_partial_minmax<<<GPART, 256>>>(X, n);
    k_nop<<<1, 32>>>();   // aligns ncu -s 5 onto pinn_kernel

    int blocks = (n + 31) / 32;   // 32 points per block
    pinn_kernel<<<blocks, NTHREADS>>>(X, lam1, lam2, out, n);
}